// round 16
// baseline (speedup 1.0000x reference)
#include <cuda_runtime.h>
#include <cuda_bf16.h>
#include <cuda_fp16.h>
#include <math.h>

#define NN 8192
#define DD 64
#define EE 262144
#define HSIZE (1u << 19)
#define HMASK (HSIZE - 1u)
#define HEMPTY 0xFFFFFFFFFFFFFFFFull

// ===================== base-ISA tensor primitives =====================
#define MMA_BF16(C, A, B0, B1) \
    asm volatile("mma.sync.aligned.m16n8k16.row.col.f32.bf16.bf16.f32 " \
        "{%0,%1,%2,%3}, {%4,%5,%6,%7}, {%8,%9}, {%0,%1,%2,%3};" \
        : "+f"((C)[0]), "+f"((C)[1]), "+f"((C)[2]), "+f"((C)[3]) \
        : "r"((A)[0]), "r"((A)[1]), "r"((A)[2]), "r"((A)[3]), "r"(B0), "r"(B1))

#define MMA_F16(C, A, B0, B1) \
    asm volatile("mma.sync.aligned.m16n8k16.row.col.f32.f16.f16.f32 " \
        "{%0,%1,%2,%3}, {%4,%5,%6,%7}, {%8,%9}, {%0,%1,%2,%3};" \
        : "+f"((C)[0]), "+f"((C)[1]), "+f"((C)[2]), "+f"((C)[3]) \
        : "r"((A)[0]), "r"((A)[1]), "r"((A)[2]), "r"((A)[3]), "r"(B0), "r"(B1))

#define LDSM4(R, addr) \
    asm volatile("ldmatrix.sync.aligned.m8n8.x4.shared.b16 {%0,%1,%2,%3}, [%4];" \
        : "=r"((R)[0]), "=r"((R)[1]), "=r"((R)[2]), "=r"((R)[3]) : "r"(addr))

#define CPA16(dst, src) \
    asm volatile("cp.async.cg.shared.global [%0], [%1], 16;" :: "r"(dst), "l"(src))
#define CP_COMMIT() asm volatile("cp.async.commit_group;" ::: "memory")
#define CP_WAIT0()  asm volatile("cp.async.wait_group 0;" ::: "memory")

__device__ __forceinline__ unsigned pack_bf16x2(float lo, float hi) {
    unsigned r;
    asm("cvt.rn.bf16x2.f32 %0, %1, %2;" : "=r"(r) : "f"(hi), "f"(lo));
    return r;
}

// ===================== static device scratch =====================
__device__ float g_G[NN * 128];                 // fp32 G (corr exact scores)
__device__ __half g_Gh[NN * 128];               // fp16 G (S matmul)
__device__ __nv_bfloat16 g_Vth[128 * NN];       // V^T bf16 (PV matmul)
__device__ float g_ediag[NN];                   // exp(||mag_i||^2)
__device__ float g_rsum[NN];
__device__ float g_accm[NN * DD];
__device__ float g_accp[NN * DD];
__device__ unsigned long long g_hash[HSIZE];
__device__ float g_escore[EE];
__device__ int   g_ne;
__device__ int   g_csrc[EE];
__device__ int   g_cdst[EE];
__device__ float g_cbias[EE];
__device__ float g_wsum4[4];
__device__ float g_bsum;
__device__ int   g_idx64;

// ===================== small kernels =====================
__global__ void k_wsum(const float* __restrict__ W, const float* __restrict__ b,
                       const unsigned* __restrict__ ei) {
    __shared__ float red[5][64];
    int t = threadIdx.x;
    red[0][t] = W[t * 4 + 0];
    red[1][t] = W[t * 4 + 1];
    red[2][t] = W[t * 4 + 2];
    red[3][t] = W[t * 4 + 3];
    red[4][t] = b[t];
    __syncthreads();
    if (t < 5) {
        float s = 0.f;
        #pragma unroll
        for (int i = 0; i < 64; i++) s += red[t][i];
        if (t < 4) g_wsum4[t] = s;
        else       g_bsum = s;
    }
    if (t == 0) {
        int all0 = 1;
        #pragma unroll
        for (int i = 1; i < 64; i += 2)
            if (ei[i] != 0u) all0 = 0;
        g_idx64 = all0;
    }
}

// G build + ediag (fused, warp per row)
__global__ void k_prep(const float* __restrict__ mag, const float* __restrict__ phase) {
    int w = (blockIdx.x * blockDim.x + threadIdx.x) >> 5;   // row
    int lane = threadIdx.x & 31;
    float2 m  = *(const float2*)(mag + w * 64 + lane * 2);
    float2 ph = *(const float2*)(phase + w * 64 + lane * 2);
    float s0, c0, s1, c1;
    sincosf(ph.x, &s0, &c0);
    sincosf(ph.y, &s1, &c1);
    float gc0 = m.x * c0, gc1 = m.y * c1, gs0 = m.x * s0, gs1 = m.y * s1;
    *(float2*)(g_G + w * 128 + lane * 2)      = make_float2(gc0, gc1);
    *(float2*)(g_G + w * 128 + 64 + lane * 2) = make_float2(gs0, gs1);
    __half2* gh = (__half2*)(g_Gh + w * 128);
    gh[lane]      = __floats2half2_rn(gc0, gc1);
    gh[32 + lane] = __floats2half2_rn(gs0, gs1);
    float s = m.x * m.x + m.y * m.y;
    #pragma unroll
    for (int o = 16; o; o >>= 1) s += __shfl_xor_sync(0xffffffffu, s, o);
    if (lane == 0) g_ediag[w] = __expf(s);
}

// transpose [k][d] -> Vt[d][k] bf16 (32x32 tiles)
__global__ void k_prepv(const float* __restrict__ mag, const float* __restrict__ phase) {
    __shared__ float t[32][33];
    int k0 = blockIdx.x * 32;
    int d0 = blockIdx.y * 32;
    int tx = threadIdx.x & 31, ty = threadIdx.x >> 5;
    const float* src = (d0 < 64) ? mag : phase;
    int dcol = (d0 < 64) ? d0 : d0 - 64;
    #pragma unroll
    for (int r = 0; r < 4; r++) {
        int k = k0 + ty + r * 8;
        t[ty + r * 8][tx] = src[k * 64 + dcol + tx];
    }
    __syncthreads();
    #pragma unroll
    for (int r = 0; r < 4; r++) {
        int d = d0 + ty + r * 8;
        g_Vth[d * NN + k0 + tx] = __float2bfloat16(t[tx][ty + r * 8]);
    }
}

// ---- edge scores + lock-free dedupe (1 edge/thread: max warps for latency hiding) ----
__global__ void k_edge(const void* __restrict__ eiv, const float* __restrict__ ea) {
    int e = blockIdx.x * blockDim.x + threadIdx.x;
    if (e >= EE) return;
    int src, dst;
    if (g_idx64) {
        const long long* ei = (const long long*)eiv;
        src = (int)ei[e];
        dst = (int)ei[EE + e];
    } else {
        const int* ei = (const int*)eiv;
        src = ei[e];
        dst = ei[EE + e];
    }
    src &= 8191; dst &= 8191;

    float4 a = ((const float4*)ea)[e];
    float score = a.x * g_wsum4[0] + a.y * g_wsum4[1] + a.z * g_wsum4[2] + a.w * g_wsum4[3] + g_bsum;
    g_escore[e] = score;

    unsigned key = ((unsigned)src << 13) | (unsigned)dst;
    unsigned long long entry = ((unsigned long long)key << 32) | (unsigned)e;
    unsigned h = key * 0x9E3779B1u;
    h ^= h >> 15;
    h &= HMASK;
    for (;;) {
        unsigned long long cur = g_hash[h];
        if (cur == HEMPTY) {
            unsigned long long prev = atomicCAS(&g_hash[h], HEMPTY, entry);
            if (prev == HEMPTY) break;
            cur = prev;
        }
        if ((unsigned)(cur >> 32) == key) {
            atomicMax(&g_hash[h], entry);
            break;
        }
        h = (h + 1) & HMASK;
    }
}

// ---- compact: 2 hash entries per thread (memory-bound scan) ----
__global__ void k_compact() {
    unsigned t = blockIdx.x * blockDim.x + threadIdx.x;
    ulonglong2 pair = ((const ulonglong2*)g_hash)[t];
    #pragma unroll
    for (int i = 0; i < 2; i++) {
        unsigned long long cur = (i == 0) ? pair.x : pair.y;
        if (cur == HEMPTY) continue;
        unsigned key = (unsigned)(cur >> 32);
        unsigned e   = (unsigned)(cur & 0xFFFFFFFFu);
        int pos = atomicAdd(&g_ne, 1);
        g_csrc[pos]  = (int)(key >> 13);
        g_cdst[pos]  = (int)(key & 8191u);
        g_cbias[pos] = g_escore[e];
    }
}

// ===================== mma.sync flash attention =====================
// grid=1024: qb = bid>>4 (128 q rows), ks = bid&15 (split-K 1/16 = 512 keys)
// Fine split-K fills all 148 SMs via scheduler backfill (wave-quantization fix).
#define QSTR 272
#define VSTR 144
#define SQH  0
#define BUF0 34816
#define BUFS 35840
#define KH_O 0
#define VH_O 17408
#define SMEMSZ (BUF0 + 2 * BUFS)   // 106496
#define NITER 8

__global__ void __launch_bounds__(256, 2)
k_attn() {
    extern __shared__ __align__(1024) char smem[];
    unsigned sb;
    asm("{ .reg .u64 t; cvta.to.shared.u64 t, %1; cvt.u32.u64 %0, t; }"
        : "=r"(sb) : "l"(smem));

    const int tid = threadIdx.x;
    const int lane = tid & 31;
    const int wid = tid >> 5;
    const int qb = blockIdx.x >> 4;
    const int ks = blockIdx.x & 15;
    const int m0 = wid * 16;

    {
        const __half* ghq = g_Gh + (qb * 128) * 128;
        for (int i = tid; i < 2048; i += 256) {
            int r = i >> 4, c = i & 15;
            CPA16(sb + SQH + r * QSTR + c * 16, (const char*)(ghq + r * 128 + c * 8));
        }
    }
    {
        int kbase = ks * 512;
        unsigned bo = sb + BUF0;
        for (int i = tid; i < 1024; i += 256) {
            int r = i >> 4, c = i & 15;
            CPA16(bo + KH_O + r * QSTR + c * 16, (const char*)(g_Gh + (kbase + r) * 128 + c * 8));
        }
        for (int i = tid; i < 1024; i += 256) {
            int d = i >> 3, c = i & 7;
            CPA16(bo + VH_O + d * VSTR + c * 16, (const char*)(g_Vth + d * NN + kbase + c * 8));
        }
    }
    CP_COMMIT();
    CP_WAIT0();
    __syncthreads();

    const unsigned aoff = (unsigned)(m0 + (lane & 15)) * QSTR + (unsigned)(lane >> 4) * 16;
    const unsigned brow = (unsigned)((lane & 7) + ((lane >> 4) << 3));
    const unsigned bc16 = (unsigned)((lane >> 3) & 1) * 16;
    const unsigned kboff = brow * QSTR + bc16;
    const unsigned vboff = brow * VSTR + bc16;

    float O[16][4];
    #pragma unroll
    for (int j = 0; j < 16; j++)
        #pragma unroll
        for (int i = 0; i < 4; i++) O[j][i] = 0.f;
    float rs_lo = 0.f, rs_hi = 0.f;

    for (int it = 0; it < NITER; it++) {
        unsigned cur = sb + BUF0 + (unsigned)(it & 1) * BUFS;

        if (it + 1 < NITER) {
            int kbase = ks * 512 + (it + 1) * 64;
            unsigned bo = sb + BUF0 + (unsigned)((it + 1) & 1) * BUFS;
            for (int i = tid; i < 1024; i += 256) {
                int r = i >> 4, c = i & 15;
                CPA16(bo + KH_O + r * QSTR + c * 16, (const char*)(g_Gh + (kbase + r) * 128 + c * 8));
            }
            for (int i = tid; i < 1024; i += 256) {
                int d = i >> 3, c = i & 7;
                CPA16(bo + VH_O + d * VSTR + c * 16, (const char*)(g_Vth + d * NN + kbase + c * 8));
            }
        }
        CP_COMMIT();

        float S[8][4];
        #pragma unroll
        for (int j = 0; j < 8; j++)
            #pragma unroll
            for (int i = 0; i < 4; i++) S[j][i] = 0.f;

        #pragma unroll
        for (int kk = 0; kk < 8; kk++) {
            unsigned k2 = kk * 32;
            unsigned qf[4];
            LDSM4(qf, sb + SQH + aoff + k2);
            #pragma unroll
            for (int nt = 0; nt < 4; nt++) {
                unsigned kh[4];
                LDSM4(kh, cur + KH_O + (unsigned)(nt * 16) * QSTR + kboff + k2);
                MMA_F16(S[2 * nt],     qf, kh[0], kh[1]);
                MMA_F16(S[2 * nt + 1], qf, kh[2], kh[3]);
            }
        }

        unsigned AH[4][4];
        #pragma unroll
        for (int j = 0; j < 8; j++) {
            int c = j >> 1, o = (j & 1) * 2;
            unsigned p01 = pack_bf16x2(__expf(S[j][0]), __expf(S[j][1]));
            unsigned p23 = pack_bf16x2(__expf(S[j][2]), __expf(S[j][3]));
            AH[c][o]     = p01;
            AH[c][o + 1] = p23;
            rs_lo += __uint_as_float(p01 << 16) + __uint_as_float(p01 & 0xffff0000u);
            rs_hi += __uint_as_float(p23 << 16) + __uint_as_float(p23 & 0xffff0000u);
        }

        #pragma unroll
        for (int c = 0; c < 4; c++) {
            unsigned k2 = c * 32;
            #pragma unroll
            for (int nt = 0; nt < 8; nt++) {
                unsigned vh[4];
                LDSM4(vh, cur + VH_O + (unsigned)(nt * 16) * VSTR + vboff + k2);
                MMA_BF16(O[2 * nt],     AH[c], vh[0], vh[1]);
                MMA_BF16(O[2 * nt + 1], AH[c], vh[2], vh[3]);
            }
        }

        CP_WAIT0();
        __syncthreads();
    }

    rs_lo += __shfl_xor_sync(0xffffffffu, rs_lo, 1);
    rs_lo += __shfl_xor_sync(0xffffffffu, rs_lo, 2);
    rs_hi += __shfl_xor_sync(0xffffffffu, rs_hi, 1);
    rs_hi += __shfl_xor_sync(0xffffffffu, rs_hi, 2);
    int r0 = qb * 128 + m0 + (lane >> 2);
    if ((lane & 3) == 0) {
        atomicAdd(&g_rsum[r0], rs_lo);
        atomicAdd(&g_rsum[r0 + 8], rs_hi);
    }

    #pragma unroll
    for (int j = 0; j < 16; j++) {
        int n = 8 * j + 2 * (lane & 3);
        float* b0 = (n < 64) ? &g_accm[r0 * 64 + n] : &g_accp[r0 * 64 + n - 64];
        float* b1 = (n < 64) ? &g_accm[(r0 + 8) * 64 + n] : &g_accp[(r0 + 8) * 64 + n - 64];
        atomicAdd(b0,     O[j][0]);
        atomicAdd(b0 + 1, O[j][1]);
        atomicAdd(b1,     O[j][2]);
        atomicAdd(b1 + 1, O[j][3]);
    }
}

// ---- sparse bias corrections: 1 edge/warp, fp32-exact, threshold skip ----
__global__ void k_corr(const float* __restrict__ mag, const float* __restrict__ phase) {
    int w = (blockIdx.x * blockDim.x + threadIdx.x) >> 5;
    int lane = threadIdx.x & 31;
    if (w >= g_ne) return;
    int src = g_csrc[w], dst = g_cdst[w];
    float bias = g_cbias[w];

    const float4* Gs = (const float4*)(g_G + src * 128);
    const float4* Gd = (const float4*)(g_G + dst * 128);
    float4 a = Gs[lane], q = Gd[lane];
    float s = a.x * q.x + a.y * q.y + a.z * q.z + a.w * q.w;
    #pragma unroll
    for (int off = 16; off; off >>= 1) s += __shfl_xor_sync(0xffffffffu, s, off);

    float delta = __expf(s) * expm1f(bias);
    if (fabsf(delta) <= 3e-7f * g_ediag[src]) return;   // uniform across warp

    if (lane == 0) atomicAdd(&g_rsum[src], delta);
    atomicAdd(&g_accm[src * 64 + lane],      delta * mag[dst * 64 + lane]);
    atomicAdd(&g_accm[src * 64 + lane + 32], delta * mag[dst * 64 + lane + 32]);
    atomicAdd(&g_accp[src * 64 + lane],      delta * phase[dst * 64 + lane]);
    atomicAdd(&g_accp[src * 64 + lane + 32], delta * phase[dst * 64 + lane + 32]);
}

// ---- normalize + diagonal Vlo correction ----
__global__ void k_norm(const float* __restrict__ mag, const float* __restrict__ phase,
                       float* __restrict__ out) {
    int tid = threadIdx.x;             // 256 = 4 rows x 64
    int sub = tid >> 6;
    int d = tid & 63;
    int row = blockIdx.x * 4 + sub;
    float m = mag[row * 64 + d];
    float p = phase[row * 64 + d];

    float pii = g_ediag[row];
    float inv = 1.f / g_rsum[row];
    float vlom = m - __bfloat162float(__float2bfloat16(m));
    float vlop = p - __bfloat162float(__float2bfloat16(p));
    out[row * 64 + d]           = (g_accm[row * 64 + d] + pii * vlom) * inv;
    out[NN * DD + row * 64 + d] = (g_accp[row * 64 + d] + pii * vlop) * inv;
}

extern "C" void kernel_launch(void* const* d_in, const int* in_sizes, int n_in,
                              void* d_out, int out_size) {
    const float* mag   = (const float*)d_in[0];
    const float* phase = (const float*)d_in[1];
    const void*  ei    = d_in[2];
    const float* ea    = (const float*)d_in[3];
    const float* W     = (const float*)d_in[4];
    const float* b     = (const float*)d_in[5];
    float* out = (float*)d_out;

    static cudaStream_t s2 = nullptr, s3 = nullptr;
    static cudaEvent_t eZ = nullptr, eV = nullptr, ePrep = nullptr, eJoin = nullptr, eFork = nullptr;
    if (!s2) {
        cudaStreamCreateWithFlags(&s2, cudaStreamNonBlocking);
        cudaStreamCreateWithFlags(&s3, cudaStreamNonBlocking);
        cudaEventCreateWithFlags(&eZ,    cudaEventDisableTiming);
        cudaEventCreateWithFlags(&eV,    cudaEventDisableTiming);
        cudaEventCreateWithFlags(&ePrep, cudaEventDisableTiming);
        cudaEventCreateWithFlags(&eJoin, cudaEventDisableTiming);
        cudaEventCreateWithFlags(&eFork, cudaEventDisableTiming);
    }

    cudaFuncSetAttribute(k_attn, cudaFuncAttributeMaxDynamicSharedMemorySize, SMEMSZ);

    void *p_hash, *p_accm, *p_accp, *p_rsum, *p_ne;
    cudaGetSymbolAddress(&p_hash, g_hash);
    cudaGetSymbolAddress(&p_accm, g_accm);
    cudaGetSymbolAddress(&p_accp, g_accp);
    cudaGetSymbolAddress(&p_rsum, g_rsum);
    cudaGetSymbolAddress(&p_ne,   g_ne);

    cudaEventRecord(eFork, 0);
    cudaStreamWaitEvent(s2, eFork, 0);
    cudaStreamWaitEvent(s3, eFork, 0);

    // ---- s3: V transpose (needed only by k_attn) ----
    dim3 gv(NN / 32, 4);
    k_prepv<<<gv, 256, 0, s3>>>(mag, phase);
    cudaEventRecord(eV, s3);

    // ---- s2: accumulator zeroing, then edge chain ----
    cudaMemsetAsync(p_accm, 0, NN * DD * sizeof(float), s2);
    cudaMemsetAsync(p_accp, 0, NN * DD * sizeof(float), s2);
    cudaMemsetAsync(p_rsum, 0, NN * sizeof(float), s2);
    cudaEventRecord(eZ, s2);
    cudaMemsetAsync(p_hash, 0xFF, HSIZE * sizeof(unsigned long long), s2);
    cudaMemsetAsync(p_ne,   0, sizeof(int), s2);
    k_wsum<<<1, 64, 0, s2>>>(W, b, (const unsigned*)ei);
    k_edge<<<EE / 256, 256, 0, s2>>>(ei, ea);
    k_compact<<<HSIZE / 512, 256, 0, s2>>>();

    // ---- main: G build; then attn once V + zeros are ready ----
    k_prep<<<NN / 8, 256>>>(mag, phase);
    cudaEventRecord(ePrep, 0);

    cudaStreamWaitEvent(s2, ePrep, 0);          // corr needs g_G/g_ediag
    k_corr<<<EE / 8, 256, 0, s2>>>(mag, phase);
    cudaEventRecord(eJoin, s2);

    cudaStreamWaitEvent(0, eZ, 0);
    cudaStreamWaitEvent(0, eV, 0);
    k_attn<<<1024, 256, SMEMSZ>>>();

    cudaStreamWaitEvent(0, eJoin, 0);
    k_norm<<<NN / 4, 256>>>(mag, phase, out);
}